// round 7
// baseline (speedup 1.0000x reference)
#include <cuda_runtime.h>
#include <cstdint>

#define D 128
#define NG 64
#define CO 16
#define MAXN 50176
#define MAXE 600064
#define NEG 0.1f
#define SCAN_CHUNK 1024
#define AST 132   // padded smem row stride (floats): bank = row*4+col -> conflict-free frags

// -------- scratch (device globals: allocation-free workaround) --------
__device__ float g_h1[MAXN * D];
__device__ float g_h2[MAXN * D];
__device__ float g_Bhi[D * D];
__device__ float g_Blo[D * D];
__device__ float g_dinv[MAXN];
__device__ int   g_degi[MAXN];
__device__ int   g_rowptr[MAXN + 1];
__device__ int   g_fill[MAXN];
__device__ int   g_csr_src[MAXE];
__device__ int   g_part[64];
__device__ float g_pool[NG * D];
__device__ float g_cnt[NG];

__device__ __forceinline__ float lrelu(float v) {
    return v >= 0.0f ? v : NEG * v;
}
__device__ __forceinline__ uint32_t tf32bits(float x) {
    uint32_t u;
    asm("cvt.rna.tf32.f32 %0, %1;" : "=r"(u) : "f"(x));
    return u;
}
__device__ __forceinline__ void mma8(float* c, const uint32_t* a, uint32_t b0, uint32_t b1) {
    asm volatile(
        "mma.sync.aligned.m16n8k8.row.col.f32.tf32.tf32.f32 "
        "{%0,%1,%2,%3}, {%4,%5,%6,%7}, {%8,%9}, {%0,%1,%2,%3};"
        : "+f"(c[0]), "+f"(c[1]), "+f"(c[2]), "+f"(c[3])
        : "r"(a[0]), "r"(a[1]), "r"(a[2]), "r"(a[3]), "r"(b0), "r"(b1));
}

// -------- W split: Bhi/Blo[n,k] = tf32-split of W[k,n] --------
__global__ void k_tr(const float* __restrict__ W,
                     float* __restrict__ BH, float* __restrict__ BL) {
    int i = blockIdx.x * 256 + threadIdx.x;   // 16384 total
    int nn = i >> 7, k = i & 127;
    float w = W[k * D + nn];
    float hi = __uint_as_float(tf32bits(w));
    BH[i] = hi;
    BL[i] = __uint_as_float(tf32bits(w - hi));
}

// ===================== tf32x3 HMMA GEMM (4m x 2n warp grid) =====================
// out[n,128] = A[n,128] @ W[128,128]. CTA = 128 rows; warp = 32 rows x 64 cols.
__global__ void __launch_bounds__(256, 1)
k_gemm_mma(const float* __restrict__ A, const float* __restrict__ BhiG,
           const float* __restrict__ BloG, float* __restrict__ out, int n) {
    extern __shared__ float sm[];
    float* As = sm;                 // 128 x AST
    float* Bh = sm + 128 * AST;     // 128 x AST   [n][k], tf32-rounded
    float* Bl = Bh + 128 * AST;     // 128 x AST

    int t = threadIdx.x;
    int r0 = blockIdx.x * 128;
    int rows = n - r0;
    if (rows > 128) rows = 128;

    const float4* A4 = (const float4*)(A + (size_t)r0 * D);
    for (int i = t; i < 128 * 32; i += 256) {
        int row = i >> 5, c4 = i & 31;
        float4 v = (row < rows) ? A4[row * 32 + c4] : make_float4(0.f, 0.f, 0.f, 0.f);
        *(float4*)&As[row * AST + c4 * 4] = v;
        *(float4*)&Bh[row * AST + c4 * 4] = ((const float4*)BhiG)[i];
        *(float4*)&Bl[row * AST + c4 * 4] = ((const float4*)BloG)[i];
    }
    __syncthreads();

    int wid = t >> 5, lane = t & 31;
    int gid = lane >> 2, tig = lane & 3;
    int wm = wid >> 1, wn = wid & 1;          // 4 m-groups x 2 n-groups

    float acc[2][8][4];
    #pragma unroll
    for (int s = 0; s < 2; s++)
        #pragma unroll
        for (int nt = 0; nt < 8; nt++)
            #pragma unroll
            for (int q = 0; q < 4; q++) acc[s][nt][q] = 0.0f;

    // A rows for the two 16-row subtiles of this warp
    const float* a00 = &As[(wm * 32 + gid) * AST];
    const float* a01 = &As[(wm * 32 + gid + 8) * AST];
    const float* a10 = &As[(wm * 32 + 16 + gid) * AST];
    const float* a11 = &As[(wm * 32 + 24 + gid) * AST];

    #pragma unroll 2
    for (int k8 = 0; k8 < D; k8 += 8) {
        float v0 = a00[k8 + tig], v1 = a01[k8 + tig];
        float v2 = a00[k8 + tig + 4], v3 = a01[k8 + tig + 4];
        float u0 = a10[k8 + tig], u1 = a11[k8 + tig];
        float u2 = a10[k8 + tig + 4], u3 = a11[k8 + tig + 4];
        uint32_t ah0[4], al0[4], ah1[4], al1[4];
        ah0[0] = tf32bits(v0); al0[0] = tf32bits(v0 - __uint_as_float(ah0[0]));
        ah0[1] = tf32bits(v1); al0[1] = tf32bits(v1 - __uint_as_float(ah0[1]));
        ah0[2] = tf32bits(v2); al0[2] = tf32bits(v2 - __uint_as_float(ah0[2]));
        ah0[3] = tf32bits(v3); al0[3] = tf32bits(v3 - __uint_as_float(ah0[3]));
        ah1[0] = tf32bits(u0); al1[0] = tf32bits(u0 - __uint_as_float(ah1[0]));
        ah1[1] = tf32bits(u1); al1[1] = tf32bits(u1 - __uint_as_float(ah1[1]));
        ah1[2] = tf32bits(u2); al1[2] = tf32bits(u2 - __uint_as_float(ah1[2]));
        ah1[3] = tf32bits(u3); al1[3] = tf32bits(u3 - __uint_as_float(ah1[3]));

        #pragma unroll
        for (int nt = 0; nt < 8; nt++) {
            int brow = (wn * 64 + nt * 8 + gid) * AST + k8;
            uint32_t bh0 = __float_as_uint(Bh[brow + tig]);
            uint32_t bh1 = __float_as_uint(Bh[brow + tig + 4]);
            uint32_t bl0 = __float_as_uint(Bl[brow + tig]);
            uint32_t bl1 = __float_as_uint(Bl[brow + tig + 4]);
            mma8(acc[0][nt], ah0, bh0, bh1);
            mma8(acc[0][nt], al0, bh0, bh1);
            mma8(acc[0][nt], ah0, bl0, bl1);
            mma8(acc[1][nt], ah1, bh0, bh1);
            mma8(acc[1][nt], al1, bh0, bh1);
            mma8(acc[1][nt], ah1, bl0, bl1);
        }
    }

    // epilogue: subtile s rows wm*32+s*16+{gid, gid+8}, cols wn*64+nt*8+tig*2
    #pragma unroll
    for (int s = 0; s < 2; s++) {
        int m0 = wm * 32 + s * 16 + gid;
        int m1 = m0 + 8;
        float* o0 = out + (size_t)(r0 + m0) * D + wn * 64;
        float* o1 = out + (size_t)(r0 + m1) * D + wn * 64;
        #pragma unroll
        for (int nt = 0; nt < 8; nt++) {
            int c = nt * 8 + tig * 2;
            if (m0 < rows) *(float2*)&o0[c] = make_float2(acc[s][nt][0], acc[s][nt][1]);
            if (m1 < rows) *(float2*)&o1[c] = make_float2(acc[s][nt][2], acc[s][nt][3]);
        }
    }
}

// ===================== CSR build =====================
__global__ void k_init(int n) {
    int stride = gridDim.x * blockDim.x;
    int i0 = blockIdx.x * blockDim.x + threadIdx.x;
    for (int i = i0; i < n; i += stride) g_degi[i] = 0;
    for (int i = i0; i < NG * D; i += stride) g_pool[i] = 0.0f;
    for (int i = i0; i < NG; i += stride) g_cnt[i] = 0.0f;
}

// histogram over dst + graph node counts (fused)
__global__ void k_hist(const int* __restrict__ dst, const int* __restrict__ batch,
                       int E, int n) {
    int stride = gridDim.x * blockDim.x;
    int i0 = blockIdx.x * blockDim.x + threadIdx.x;
    for (int e = i0; e < E; e += stride)
        atomicAdd(&g_degi[dst[e]], 1);
    for (int i = i0; i < n; i += stride)
        atomicAdd(&g_cnt[batch[i]], 1.0f);
}

__global__ void k_scanA(int n) {
    __shared__ int red[8];
    int t = threadIdx.x;
    int base = blockIdx.x * SCAN_CHUNK;
    int s = 0;
    #pragma unroll
    for (int j = 0; j < 4; j++) {
        int i = base + t + j * 256;
        if (i < n) s += g_degi[i];
    }
    #pragma unroll
    for (int off = 16; off; off >>= 1) s += __shfl_down_sync(~0u, s, off);
    if ((t & 31) == 0) red[t >> 5] = s;
    __syncthreads();
    if (t == 0) {
        int tot = 0;
        #pragma unroll
        for (int w = 0; w < 8; w++) tot += red[w];
        g_part[blockIdx.x] = tot;
    }
}

__global__ void k_scanB(int nblk, int n) {
    __shared__ int sm[64];
    int t = threadIdx.x;
    int v = (t < nblk) ? g_part[t] : 0;
    sm[t] = v;
    __syncthreads();
    #pragma unroll
    for (int off = 1; off < 64; off <<= 1) {
        int u = (t >= off) ? sm[t - off] : 0;
        __syncthreads();
        sm[t] += u;
        __syncthreads();
    }
    if (t < nblk) g_part[t] = (t == 0) ? 0 : sm[t - 1];
    if (t == 63) g_rowptr[n] = sm[63];
}

__global__ void k_scanC(int n) {
    __shared__ int sm[SCAN_CHUNK];
    int t = threadIdx.x;
    int i = blockIdx.x * SCAN_CHUNK + t;
    int d = (i < n) ? g_degi[i] : 0;
    sm[t] = d;
    __syncthreads();
    #pragma unroll
    for (int off = 1; off < SCAN_CHUNK; off <<= 1) {
        int u = (t >= off) ? sm[t - off] : 0;
        __syncthreads();
        sm[t] += u;
        __syncthreads();
    }
    if (i < n) {
        int excl = g_part[blockIdx.x] + sm[t] - d;
        g_rowptr[i] = excl;
        g_fill[i] = excl;
        g_dinv[i] = rsqrtf((float)d + 1.0f);
    }
}

__global__ void k_permute(const int* __restrict__ src, const int* __restrict__ dst, int E) {
    int stride = gridDim.x * blockDim.x;
    for (int e = blockIdx.x * blockDim.x + threadIdx.x; e < E; e += stride) {
        int d = dst[e];
        int pos = atomicAdd(&g_fill[d], 1);
        g_csr_src[pos] = src[e];
    }
}

// ===================== gather / pool / head =====================
__global__ void k_gcn(const float* __restrict__ h, const float* __restrict__ bias,
                      float* __restrict__ out, int n) {
    int node = blockIdx.x * 8 + (threadIdx.x >> 5);
    if (node >= n) return;
    int lane = threadIdx.x & 31;
    int beg = g_rowptr[node], end = g_rowptr[node + 1];
    float di = g_dinv[node];

    float4 acc = make_float4(0.f, 0.f, 0.f, 0.f);
    for (int e = beg; e < end; e++) {
        int s = g_csr_src[e];
        float coef = g_dinv[s] * di;
        float4 v = ((const float4*)(h + (size_t)s * D))[lane];
        acc.x += coef * v.x; acc.y += coef * v.y;
        acc.z += coef * v.z; acc.w += coef * v.w;
    }
    float4 hv = ((const float4*)(h + (size_t)node * D))[lane];
    float4 b = ((const float4*)bias)[lane];
    float d2 = di * di;
    float4 r;
    r.x = lrelu(acc.x + hv.x * d2 + b.x);
    r.y = lrelu(acc.y + hv.y * d2 + b.y);
    r.z = lrelu(acc.z + hv.z * d2 + b.z);
    r.w = lrelu(acc.w + hv.w * d2 + b.w);
    ((float4*)(out + (size_t)node * D))[lane] = r;
}

__global__ void k_gcn_pool(const float* __restrict__ h, const float* __restrict__ bias,
                           const int* __restrict__ batch, int n) {
    int node = blockIdx.x * 8 + (threadIdx.x >> 5);
    if (node >= n) return;
    int lane = threadIdx.x & 31;
    int beg = g_rowptr[node], end = g_rowptr[node + 1];
    float di = g_dinv[node];

    float4 acc = make_float4(0.f, 0.f, 0.f, 0.f);
    for (int e = beg; e < end; e++) {
        int s = g_csr_src[e];
        float coef = g_dinv[s] * di;
        float4 v = ((const float4*)(h + (size_t)s * D))[lane];
        acc.x += coef * v.x; acc.y += coef * v.y;
        acc.z += coef * v.z; acc.w += coef * v.w;
    }
    float4 hv = ((const float4*)(h + (size_t)node * D))[lane];
    float4 b = ((const float4*)bias)[lane];
    float d2 = di * di;
    float4 r;
    r.x = lrelu(acc.x + hv.x * d2 + b.x);
    r.y = lrelu(acc.y + hv.y * d2 + b.y);
    r.z = lrelu(acc.z + hv.z * d2 + b.z);
    r.w = lrelu(acc.w + hv.w * d2 + b.w);
    int gid = batch[node];
    atomicAdd(((float4*)g_pool) + gid * 32 + lane, r);
}

__global__ void k_final(const float* __restrict__ Wl, const float* __restrict__ bl,
                        float* __restrict__ out) {
    int t = threadIdx.x;
    int g = t >> 4;
    int c = t & 15;
    float cnt = fmaxf(g_cnt[g], 1.0f);
    float s = 0.0f;
    #pragma unroll 8
    for (int f = 0; f < D; f++)
        s += g_pool[g * D + f] * Wl[f * CO + c];
    out[g * CO + c] = s / cnt + bl[c];
}

extern "C" void kernel_launch(void* const* d_in, const int* in_sizes, int n_in,
                              void* d_out, int out_size) {
    const float* x     = (const float*)d_in[0];
    const int*   ei    = (const int*)d_in[1];
    const int*   batch = (const int*)d_in[2];
    const float* W1    = (const float*)d_in[3];
    const float* b1    = (const float*)d_in[4];
    const float* W2    = (const float*)d_in[5];
    const float* b2    = (const float*)d_in[6];
    const float* Wl    = (const float*)d_in[7];
    const float* bl    = (const float*)d_in[8];

    int n = in_sizes[0] / D;
    int E = in_sizes[1] / 2;
    const int* src = ei;
    const int* dst = ei + E;

    void *ph1 = nullptr, *ph2 = nullptr, *pbh = nullptr, *pbl = nullptr;
    cudaGetSymbolAddress(&ph1, g_h1);
    cudaGetSymbolAddress(&ph2, g_h2);
    cudaGetSymbolAddress(&pbh, g_Bhi);
    cudaGetSymbolAddress(&pbl, g_Blo);
    float* h1 = (float*)ph1;
    float* h2 = (float*)ph2;
    float* BH = (float*)pbh;
    float* BL = (float*)pbl;

    int smem = 3 * 128 * AST * (int)sizeof(float);   // 202752 B
    cudaFuncSetAttribute(k_gemm_mma, cudaFuncAttributeMaxDynamicSharedMemorySize, smem);

    int nblk = (n + SCAN_CHUNK - 1) / SCAN_CHUNK;
    int nblocks8 = (n + 7) / 8;
    int gtiles = (n + 127) / 128;

    // CSR build
    k_init<<<512, 256>>>(n);
    k_hist<<<1024, 256>>>(dst, batch, E, n);
    k_scanA<<<nblk, 256>>>(n);
    k_scanB<<<1, 64>>>(nblk, n);
    k_scanC<<<nblk, SCAN_CHUNK>>>(n);
    k_permute<<<1024, 256>>>(src, dst, E);

    // Layer 1: h1 = x@W1 ; h2 = gcn(h1)
    k_tr<<<64, 256>>>(W1, BH, BL);
    k_gemm_mma<<<gtiles, 256, smem>>>(x, BH, BL, h1, n);
    k_gcn<<<nblocks8, 256>>>(h1, b1, h2, n);

    // Layer 2: h1 = h2@W2 ; pool += gcn(h1)
    k_tr<<<64, 256>>>(W2, BH, BL);
    k_gemm_mma<<<gtiles, 256, smem>>>(h2, BH, BL, h1, n);
    k_gcn_pool<<<nblocks8, 256>>>(h1, b2, batch, n);

    // Head
    k_final<<<1, 1024>>>(Wl, bl, (float*)d_out);
}